// round 14
// baseline (speedup 1.0000x reference)
#include <cuda_runtime.h>
#include <math.h>
#include <stdint.h>

#define BATCH 4
#define SEQ   2048
#define DIM   2048
#define NH    16
#define DHEAD 128

__device__ float g_Q[BATCH * SEQ * DIM];
__device__ float g_K[BATCH * SEQ * DIM];
__device__ float g_V[BATCH * SEQ * DIM];
__device__ float g_A[BATCH * SEQ * DIM];

__device__ __forceinline__ unsigned f2tf32(float x) {
    unsigned u;
    asm("cvt.rna.tf32.f32 %0, %1;" : "=r"(u) : "f"(x));
    return u;
}
__device__ __forceinline__ void mma_tf32(float* d, const unsigned* a, const unsigned* b) {
    asm volatile(
        "mma.sync.aligned.m16n8k8.row.col.f32.tf32.tf32.f32 "
        "{%0,%1,%2,%3}, {%4,%5,%6,%7}, {%8,%9}, {%0,%1,%2,%3};\n"
        : "+f"(d[0]), "+f"(d[1]), "+f"(d[2]), "+f"(d[3])
        : "r"(a[0]), "r"(a[1]), "r"(a[2]), "r"(a[3]), "r"(b[0]), "r"(b[1]));
}

// ---------------------------------------------------------------------------
// TF32 NT GEMM (R6 structure: register double-buffer, one sync per k-tile,
// cvt in R2S). Fused over nz weight matrices via z = blockIdx.x >> 4,
// selected with scalar params + if/else (no dynamic param-array indexing).
// C[z] = (A @ W[z]^T + bias[z]) * gate(mode[z]); mode 0 none, 1 cos, 2 sin.
// ---------------------------------------------------------------------------
#define GSTRIDE 36
#define GBUF (128 * GSTRIDE)
#define GEMM_SMEM_BYTES (4 * GBUF * 4)   // 73728 -> 2 CTAs/SM

__global__ __launch_bounds__(256) void gemm_tf32_kernel(
    const float* __restrict__ A, const float* __restrict__ rot,
    const float* __restrict__ W0, const float* __restrict__ b0_, float* __restrict__ C0, int m0,
    const float* __restrict__ W1, const float* __restrict__ b1_, float* __restrict__ C1, int m1,
    const float* __restrict__ W2, const float* __restrict__ b2_, float* __restrict__ C2, int m2,
    int roundout)
{
    extern __shared__ unsigned sm[];
    unsigned* As = sm;
    unsigned* Bs = sm + 2 * GBUF;

    const int K = DIM, N = DIM;
    const int tid = threadIdx.x;
    const int warp = tid >> 5, lane = tid & 31;
    const int wm = (warp >> 2) * 64;
    const int wn = (warp & 3) * 32;
    const int z = blockIdx.x >> 4;
    const int bm = blockIdx.y * 128, bn = (blockIdx.x & 15) * 128;

    const float* W;  const float* bias;  float* C;  int mode;
    if (z == 0)      { W = W0; bias = b0_; C = C0; mode = m0; }
    else if (z == 1) { W = W1; bias = b1_; C = C1; mode = m1; }
    else             { W = W2; bias = b2_; C = C2; mode = m2; }

    const int lrow = tid >> 3;          // 0..31
    const int lcol = (tid & 7) * 4;     // 0..28

    float acc[4][4][4];
#pragma unroll
    for (int i = 0; i < 4; i++)
#pragma unroll
        for (int j = 0; j < 4; j++)
#pragma unroll
            for (int t = 0; t < 4; t++) acc[i][j][t] = 0.f;

    const float* Ag = A + (size_t)(bm + lrow) * K + lcol;
    const float* Wg = W + (size_t)(bn + lrow) * K + lcol;

    float4 ra[4], rb[4];

    auto G2R = [&](int kt) {
        const size_t ko = (size_t)kt * 32;
#pragma unroll
        for (int it = 0; it < 4; it++) {
            ra[it] = *(const float4*)(Ag + (size_t)it * 32 * K + ko);
            rb[it] = *(const float4*)(Wg + (size_t)it * 32 * K + ko);
        }
    };
    auto R2S = [&](int buf) {
#pragma unroll
        for (int it = 0; it < 4; it++) {
            int base = buf * GBUF + (lrow + it * 32) * GSTRIDE + lcol;
            uint4 ua = make_uint4(f2tf32(ra[it].x), f2tf32(ra[it].y),
                                  f2tf32(ra[it].z), f2tf32(ra[it].w));
            uint4 ub = make_uint4(f2tf32(rb[it].x), f2tf32(rb[it].y),
                                  f2tf32(rb[it].z), f2tf32(rb[it].w));
            *(uint4*)(As + base) = ua;
            *(uint4*)(Bs + base) = ub;
        }
    };

    const int ntiles = K / 32;   // 64
    G2R(0);
    R2S(0);
    __syncthreads();

    const int lq = lane >> 2;
    const int lr = lane & 3;

    for (int kt = 0; kt < ntiles; kt++) {
        if (kt + 1 < ntiles) G2R(kt + 1);

        const unsigned* Ab = As + (kt & 1) * GBUF;
        const unsigned* Bb = Bs + (kt & 1) * GBUF;
#pragma unroll
        for (int k8 = 0; k8 < 4; k8++) {
            const int kc = k8 * 8 + lr;
            unsigned af[4][4], bf[4][2];
#pragma unroll
            for (int i = 0; i < 4; i++) {
                int r = wm + i * 16 + lq;
                af[i][0] = Ab[r * GSTRIDE + kc];
                af[i][1] = Ab[(r + 8) * GSTRIDE + kc];
                af[i][2] = Ab[r * GSTRIDE + kc + 4];
                af[i][3] = Ab[(r + 8) * GSTRIDE + kc + 4];
            }
#pragma unroll
            for (int j = 0; j < 4; j++) {
                int c = wn + j * 8 + lq;
                bf[j][0] = Bb[c * GSTRIDE + kc];
                bf[j][1] = Bb[c * GSTRIDE + kc + 4];
            }
#pragma unroll
            for (int i = 0; i < 4; i++)
#pragma unroll
                for (int j = 0; j < 4; j++)
                    mma_tf32(acc[i][j], af[i], bf[j]);
        }

        if (kt + 1 < ntiles) R2S((kt + 1) & 1);
        __syncthreads();
    }

    // epilogue: bias + optional cos/sin gate, optional tf32 rounding
#pragma unroll
    for (int j = 0; j < 4; j++) {
        int c0 = bn + wn + j * 8 + (lr << 1);
        float bb0 = __ldg(bias + c0), bb1 = __ldg(bias + c0 + 1);
        float g0 = 1.f, g1 = 1.f;
        if (mode == 1) { g0 = cosf(__ldg(rot + c0)); g1 = cosf(__ldg(rot + c0 + 1)); }
        else if (mode == 2) { g0 = sinf(__ldg(rot + c0)); g1 = sinf(__ldg(rot + c0 + 1)); }
#pragma unroll
        for (int i = 0; i < 4; i++) {
            int r0 = bm + wm + i * 16 + lq;
            float v00 = (acc[i][j][0] + bb0) * g0, v01 = (acc[i][j][1] + bb1) * g1;
            float v10 = (acc[i][j][2] + bb0) * g0, v11 = (acc[i][j][3] + bb1) * g1;
            if (roundout) {
                v00 = __uint_as_float(f2tf32(v00)); v01 = __uint_as_float(f2tf32(v01));
                v10 = __uint_as_float(f2tf32(v10)); v11 = __uint_as_float(f2tf32(v11));
            }
            *(float2*)(C + (size_t)r0 * N + c0)       = make_float2(v00, v01);
            *(float2*)(C + (size_t)(r0 + 8) * N + c0) = make_float2(v10, v11);
        }
    }
}

// ---------------------------------------------------------------------------
// TF32 mma.sync flash attention (R6 known-good, unchanged).
// BM=64 (4 warps x 16 rows), BN=64, DH=128, 128 threads, 2 CTAs/SM.
// ---------------------------------------------------------------------------
#define KSTRIDE 132
#define FLASH_SMEM_BYTES (2 * 64 * KSTRIDE * 4)

__global__ __launch_bounds__(128) void flash_tf32_kernel(
    const float* __restrict__ Q, const float* __restrict__ K,
    const float* __restrict__ V, const float* __restrict__ spiral,
    float* __restrict__ O)
{
    extern __shared__ float fs[];
    float* sK = fs;
    float* sV = fs + 64 * KSTRIDE;

    const int tid = threadIdx.x;
    const int warp = tid >> 5, lane = tid & 31;
    const int lq = lane >> 2, lr = lane & 3;
    const int qt = blockIdx.x, h = blockIdx.y, b = blockIdx.z;
    const int s0 = qt * 64;
    const float scale = spiral[h] * 0.08838834764831845f;

    const size_t baseQ = ((size_t)b * SEQ + s0) * DIM + (size_t)h * DHEAD;
    const size_t baseK = (size_t)b * SEQ * DIM + (size_t)h * DHEAD;

    for (int idx = tid; idx < 64 * 32; idx += 128) {
        int r = idx >> 5, c4 = (idx & 31) << 2;
        *(float4*)(sK + r * KSTRIDE + c4) =
            *(const float4*)(Q + baseQ + (size_t)r * DIM + c4);
    }
    __syncthreads();

    unsigned qf[16][4];
    const int qrow = warp * 16 + lq;
#pragma unroll
    for (int ks = 0; ks < 16; ks++) {
        qf[ks][0] = __float_as_uint(sK[qrow * KSTRIDE + ks * 8 + lr]);
        qf[ks][1] = __float_as_uint(sK[(qrow + 8) * KSTRIDE + ks * 8 + lr]);
        qf[ks][2] = __float_as_uint(sK[qrow * KSTRIDE + ks * 8 + lr + 4]);
        qf[ks][3] = __float_as_uint(sK[(qrow + 8) * KSTRIDE + ks * 8 + lr + 4]);
    }
    __syncthreads();

    float o[16][4];
#pragma unroll
    for (int jn = 0; jn < 16; jn++)
#pragma unroll
        for (int t = 0; t < 4; t++) o[jn][t] = 0.f;
    float m0 = -INFINITY, m1 = -INFINITY, l0 = 0.f, l1 = 0.f;

    for (int kt = 0; kt < SEQ / 64; kt++) {
        const size_t kb = baseK + (size_t)kt * 64 * DIM;
        for (int idx = tid; idx < 64 * 32; idx += 128) {
            int r = idx >> 5, c4 = (idx & 31) << 2;
            *(float4*)(sK + r * KSTRIDE + c4) =
                *(const float4*)(K + kb + (size_t)r * DIM + c4);
            *(float4*)(sV + r * KSTRIDE + c4) =
                *(const float4*)(V + kb + (size_t)r * DIM + c4);
        }
        __syncthreads();

        float sacc[8][4];
#pragma unroll
        for (int j = 0; j < 8; j++)
#pragma unroll
            for (int t = 0; t < 4; t++) sacc[j][t] = 0.f;

#pragma unroll
        for (int ks = 0; ks < 16; ks++) {
#pragma unroll
            for (int j = 0; j < 8; j++) {
                unsigned bf[2];
                bf[0] = __float_as_uint(sK[(j * 8 + lq) * KSTRIDE + ks * 8 + lr]);
                bf[1] = __float_as_uint(sK[(j * 8 + lq) * KSTRIDE + ks * 8 + lr + 4]);
                mma_tf32(sacc[j], qf[ks], bf);
            }
        }

        float mx0 = -INFINITY, mx1 = -INFINITY;
#pragma unroll
        for (int j = 0; j < 8; j++) {
            sacc[j][0] *= scale; sacc[j][1] *= scale;
            sacc[j][2] *= scale; sacc[j][3] *= scale;
            mx0 = fmaxf(mx0, fmaxf(sacc[j][0], sacc[j][1]));
            mx1 = fmaxf(mx1, fmaxf(sacc[j][2], sacc[j][3]));
        }
        mx0 = fmaxf(mx0, __shfl_xor_sync(0xffffffffu, mx0, 1));
        mx0 = fmaxf(mx0, __shfl_xor_sync(0xffffffffu, mx0, 2));
        mx1 = fmaxf(mx1, __shfl_xor_sync(0xffffffffu, mx1, 1));
        mx1 = fmaxf(mx1, __shfl_xor_sync(0xffffffffu, mx1, 2));

        float mn0 = fmaxf(m0, mx0), mn1 = fmaxf(m1, mx1);
        float al0 = __expf(m0 - mn0), al1 = __expf(m1 - mn1);
        m0 = mn0; m1 = mn1;

        unsigned pb[8][4];
        float sum0 = 0.f, sum1 = 0.f;
#pragma unroll
        for (int j = 0; j < 8; j++) {
            float p0 = __expf(sacc[j][0] - mn0);
            float p1 = __expf(sacc[j][1] - mn0);
            float p2 = __expf(sacc[j][2] - mn1);
            float p3 = __expf(sacc[j][3] - mn1);
            sum0 += p0 + p1; sum1 += p2 + p3;
            pb[j][0] = f2tf32(p0); pb[j][1] = f2tf32(p1);
            pb[j][2] = f2tf32(p2); pb[j][3] = f2tf32(p3);
        }
        sum0 += __shfl_xor_sync(0xffffffffu, sum0, 1);
        sum0 += __shfl_xor_sync(0xffffffffu, sum0, 2);
        sum1 += __shfl_xor_sync(0xffffffffu, sum1, 1);
        sum1 += __shfl_xor_sync(0xffffffffu, sum1, 2);
        l0 = l0 * al0 + sum0;
        l1 = l1 * al1 + sum1;

#pragma unroll
        for (int jn = 0; jn < 16; jn++) {
            o[jn][0] *= al0; o[jn][1] *= al0;
            o[jn][2] *= al1; o[jn][3] *= al1;
        }

        const int srcl = lq * 4 + (lr >> 1);
#pragma unroll
        for (int k8 = 0; k8 < 8; k8++) {
            unsigned a[4];
            unsigned t00 = __shfl_sync(0xffffffffu, pb[k8][0], srcl);
            unsigned t01 = __shfl_sync(0xffffffffu, pb[k8][1], srcl);
            unsigned t10 = __shfl_sync(0xffffffffu, pb[k8][2], srcl);
            unsigned t11 = __shfl_sync(0xffffffffu, pb[k8][3], srcl);
            unsigned u00 = __shfl_sync(0xffffffffu, pb[k8][0], srcl + 2);
            unsigned u01 = __shfl_sync(0xffffffffu, pb[k8][1], srcl + 2);
            unsigned u10 = __shfl_sync(0xffffffffu, pb[k8][2], srcl + 2);
            unsigned u11 = __shfl_sync(0xffffffffu, pb[k8][3], srcl + 2);
            a[0] = (lr & 1) ? t01 : t00;
            a[1] = (lr & 1) ? t11 : t10;
            a[2] = (lr & 1) ? u01 : u00;
            a[3] = (lr & 1) ? u11 : u10;
#pragma unroll
            for (int jn = 0; jn < 16; jn++) {
                unsigned bf[2];
                bf[0] = __float_as_uint(sV[(k8 * 8 + lr) * KSTRIDE + jn * 8 + lq]);
                bf[1] = __float_as_uint(sV[(k8 * 8 + lr + 4) * KSTRIDE + jn * 8 + lq]);
                mma_tf32(o[jn], a, bf);
            }
        }
        __syncthreads();
    }

    const float inv0 = 1.0f / l0, inv1 = 1.0f / l1;
    float* Orow0 = O + baseQ + (size_t)qrow * DIM;
    float* Orow1 = O + baseQ + (size_t)(qrow + 8) * DIM;
#pragma unroll
    for (int jn = 0; jn < 16; jn++) {
        int c = jn * 8 + 2 * lr;
        *(float2*)(Orow0 + c) = make_float2(o[jn][0] * inv0, o[jn][1] * inv0);
        *(float2*)(Orow1 + c) = make_float2(o[jn][2] * inv1, o[jn][3] * inv1);
    }
}

// ---------------------------------------------------------------------------
extern "C" void kernel_launch(void* const* d_in, const int* in_sizes, int n_in,
                              void* d_out, int out_size)
{
    const float* x      = (const float*)d_in[0];
    const float* Wq     = (const float*)d_in[1];
    const float* bq     = (const float*)d_in[2];
    const float* Wk     = (const float*)d_in[3];
    const float* bk     = (const float*)d_in[4];
    const float* Wv     = (const float*)d_in[5];
    const float* bv     = (const float*)d_in[6];
    const float* Wo     = (const float*)d_in[7];
    const float* bo     = (const float*)d_in[8];
    const float* spiral = (const float*)d_in[9];
    const float* rot    = (const float*)d_in[10];
    float* out = (float*)d_out;

    float *Qp, *Kp, *Vp, *Ap;
    cudaGetSymbolAddress((void**)&Qp, g_Q);
    cudaGetSymbolAddress((void**)&Kp, g_K);
    cudaGetSymbolAddress((void**)&Vp, g_V);
    cudaGetSymbolAddress((void**)&Ap, g_A);

    const int M = BATCH * SEQ;   // 8192

    cudaFuncSetAttribute(gemm_tf32_kernel,
                         cudaFuncAttributeMaxDynamicSharedMemorySize, GEMM_SMEM_BYTES);
    cudaFuncSetAttribute(flash_tf32_kernel,
                         cudaFuncAttributeMaxDynamicSharedMemorySize, FLASH_SMEM_BYTES);

    // fused QKV projection in ONE launch: z = blockIdx.x/16 selects W/bias/C
    gemm_tf32_kernel<<<dim3(48, M / 128), 256, GEMM_SMEM_BYTES>>>(
        x, rot,
        Wq, bq, Qp, 1,
        Wk, bk, Kp, 2,
        Wv, bv, Vp, 0,
        1);

    flash_tf32_kernel<<<dim3(SEQ / 64, NH, BATCH), 128, FLASH_SMEM_BYTES>>>(
        Qp, Kp, Vp, spiral, Ap);

    // output projection (single weight; z always 0)
    gemm_tf32_kernel<<<dim3(16, M / 128), 256, GEMM_SMEM_BYTES>>>(
        Ap, rot,
        Wo, bo, out, 0,
        Wo, bo, out, 0,
        Wo, bo, out, 0,
        0);
}

// round 16
// speedup vs baseline: 1.1059x; 1.1059x over previous
#include <cuda_runtime.h>
#include <math.h>
#include <stdint.h>

#define BATCH 4
#define SEQ   2048
#define DIM   2048
#define NH    16
#define DHEAD 128

__device__ float g_Q[BATCH * SEQ * DIM];
__device__ float g_K[BATCH * SEQ * DIM];
__device__ float g_V[BATCH * SEQ * DIM];
__device__ float g_A[BATCH * SEQ * DIM];

__device__ __forceinline__ unsigned f2tf32(float x) {
    unsigned u;
    asm("cvt.rna.tf32.f32 %0, %1;" : "=r"(u) : "f"(x));
    return u;
}
__device__ __forceinline__ void mma_tf32(float* d, const unsigned* a, const unsigned* b) {
    asm volatile(
        "mma.sync.aligned.m16n8k8.row.col.f32.tf32.tf32.f32 "
        "{%0,%1,%2,%3}, {%4,%5,%6,%7}, {%8,%9}, {%0,%1,%2,%3};\n"
        : "+f"(d[0]), "+f"(d[1]), "+f"(d[2]), "+f"(d[3])
        : "r"(a[0]), "r"(a[1]), "r"(a[2]), "r"(a[3]), "r"(b[0]), "r"(b[1]));
}

// ---------------------------------------------------------------------------
// TF32 NT GEMM (R6 inner loop). Fused over up to 3 weight matrices via
// z = blockIdx.x >> 4 with scalar params + if/else.
// __launch_bounds__(256, 2) caps regs at 128 -> guarantees 2 CTAs/SM.
// C[z] = (A @ W[z]^T + bias[z]) * gate(mode[z]); mode 0 none, 1 cos, 2 sin.
// ---------------------------------------------------------------------------
#define GSTRIDE 36
#define GBUF (128 * GSTRIDE)
#define GEMM_SMEM_BYTES (4 * GBUF * 4)   // 73728 -> fits 2 CTAs/SM

__global__ __launch_bounds__(256, 2) void gemm_tf32_kernel(
    const float* __restrict__ A, const float* __restrict__ rot,
    const float* __restrict__ W0, const float* __restrict__ b0_, float* __restrict__ C0, int m0,
    const float* __restrict__ W1, const float* __restrict__ b1_, float* __restrict__ C1, int m1,
    const float* __restrict__ W2, const float* __restrict__ b2_, float* __restrict__ C2, int m2,
    int roundout)
{
    extern __shared__ unsigned sm[];
    unsigned* As = sm;
    unsigned* Bs = sm + 2 * GBUF;

    const int K = DIM, N = DIM;
    const int tid = threadIdx.x;
    const int warp = tid >> 5, lane = tid & 31;
    const int wm = (warp >> 2) * 64;
    const int wn = (warp & 3) * 32;
    const int z = blockIdx.x >> 4;
    const int bm = blockIdx.y * 128, bn = (blockIdx.x & 15) * 128;

    const float* W;  const float* bias;  float* C;  int mode;
    if (z == 0)      { W = W0; bias = b0_; C = C0; mode = m0; }
    else if (z == 1) { W = W1; bias = b1_; C = C1; mode = m1; }
    else             { W = W2; bias = b2_; C = C2; mode = m2; }

    const int lrow = tid >> 3;          // 0..31
    const int lcol = (tid & 7) * 4;     // 0..28

    float acc[4][4][4];
#pragma unroll
    for (int i = 0; i < 4; i++)
#pragma unroll
        for (int j = 0; j < 4; j++)
#pragma unroll
            for (int t = 0; t < 4; t++) acc[i][j][t] = 0.f;

    const float* Ag = A + (size_t)(bm + lrow) * K + lcol;
    const float* Wg = W + (size_t)(bn + lrow) * K + lcol;

    float4 ra[4], rb[4];

    auto G2R = [&](int kt) {
        const size_t ko = (size_t)kt * 32;
#pragma unroll
        for (int it = 0; it < 4; it++) {
            ra[it] = *(const float4*)(Ag + (size_t)it * 32 * K + ko);
            rb[it] = *(const float4*)(Wg + (size_t)it * 32 * K + ko);
        }
    };
    auto R2S = [&](int buf) {
#pragma unroll
        for (int it = 0; it < 4; it++) {
            int base = buf * GBUF + (lrow + it * 32) * GSTRIDE + lcol;
            uint4 ua = make_uint4(f2tf32(ra[it].x), f2tf32(ra[it].y),
                                  f2tf32(ra[it].z), f2tf32(ra[it].w));
            uint4 ub = make_uint4(f2tf32(rb[it].x), f2tf32(rb[it].y),
                                  f2tf32(rb[it].z), f2tf32(rb[it].w));
            *(uint4*)(As + base) = ua;
            *(uint4*)(Bs + base) = ub;
        }
    };

    const int ntiles = K / 32;   // 64
    G2R(0);
    R2S(0);
    __syncthreads();

    const int lq = lane >> 2;
    const int lr = lane & 3;

    for (int kt = 0; kt < ntiles; kt++) {
        if (kt + 1 < ntiles) G2R(kt + 1);

        const unsigned* Ab = As + (kt & 1) * GBUF;
        const unsigned* Bb = Bs + (kt & 1) * GBUF;
#pragma unroll
        for (int k8 = 0; k8 < 4; k8++) {
            const int kc = k8 * 8 + lr;
            unsigned af[4][4], bf[4][2];
#pragma unroll
            for (int i = 0; i < 4; i++) {
                int r = wm + i * 16 + lq;
                af[i][0] = Ab[r * GSTRIDE + kc];
                af[i][1] = Ab[(r + 8) * GSTRIDE + kc];
                af[i][2] = Ab[r * GSTRIDE + kc + 4];
                af[i][3] = Ab[(r + 8) * GSTRIDE + kc + 4];
            }
#pragma unroll
            for (int j = 0; j < 4; j++) {
                int c = wn + j * 8 + lq;
                bf[j][0] = Bb[c * GSTRIDE + kc];
                bf[j][1] = Bb[c * GSTRIDE + kc + 4];
            }
#pragma unroll
            for (int i = 0; i < 4; i++)
#pragma unroll
                for (int j = 0; j < 4; j++)
                    mma_tf32(acc[i][j], af[i], bf[j]);
        }

        if (kt + 1 < ntiles) R2S((kt + 1) & 1);
        __syncthreads();
    }

    // epilogue: bias + optional cos/sin gate, optional tf32 rounding
#pragma unroll
    for (int j = 0; j < 4; j++) {
        int c0 = bn + wn + j * 8 + (lr << 1);
        float bb0 = __ldg(bias + c0), bb1 = __ldg(bias + c0 + 1);
        float g0 = 1.f, g1 = 1.f;
        if (mode == 1) { g0 = cosf(__ldg(rot + c0)); g1 = cosf(__ldg(rot + c0 + 1)); }
        else if (mode == 2) { g0 = sinf(__ldg(rot + c0)); g1 = sinf(__ldg(rot + c0 + 1)); }
#pragma unroll
        for (int i = 0; i < 4; i++) {
            int r0 = bm + wm + i * 16 + lq;
            float v00 = (acc[i][j][0] + bb0) * g0, v01 = (acc[i][j][1] + bb1) * g1;
            float v10 = (acc[i][j][2] + bb0) * g0, v11 = (acc[i][j][3] + bb1) * g1;
            if (roundout) {
                v00 = __uint_as_float(f2tf32(v00)); v01 = __uint_as_float(f2tf32(v01));
                v10 = __uint_as_float(f2tf32(v10)); v11 = __uint_as_float(f2tf32(v11));
            }
            *(float2*)(C + (size_t)r0 * N + c0)       = make_float2(v00, v01);
            *(float2*)(C + (size_t)(r0 + 8) * N + c0) = make_float2(v10, v11);
        }
    }
}

// ---------------------------------------------------------------------------
// TF32 mma.sync flash attention (R6 known-good, unchanged).
// BM=64 (4 warps x 16 rows), BN=64, DH=128, 128 threads, 2 CTAs/SM.
// ---------------------------------------------------------------------------
#define KSTRIDE 132
#define FLASH_SMEM_BYTES (2 * 64 * KSTRIDE * 4)

__global__ __launch_bounds__(128) void flash_tf32_kernel(
    const float* __restrict__ Q, const float* __restrict__ K,
    const float* __restrict__ V, const float* __restrict__ spiral,
    float* __restrict__ O)
{
    extern __shared__ float fs[];
    float* sK = fs;
    float* sV = fs + 64 * KSTRIDE;

    const int tid = threadIdx.x;
    const int warp = tid >> 5, lane = tid & 31;
    const int lq = lane >> 2, lr = lane & 3;
    const int qt = blockIdx.x, h = blockIdx.y, b = blockIdx.z;
    const int s0 = qt * 64;
    const float scale = spiral[h] * 0.08838834764831845f;

    const size_t baseQ = ((size_t)b * SEQ + s0) * DIM + (size_t)h * DHEAD;
    const size_t baseK = (size_t)b * SEQ * DIM + (size_t)h * DHEAD;

    for (int idx = tid; idx < 64 * 32; idx += 128) {
        int r = idx >> 5, c4 = (idx & 31) << 2;
        *(float4*)(sK + r * KSTRIDE + c4) =
            *(const float4*)(Q + baseQ + (size_t)r * DIM + c4);
    }
    __syncthreads();

    unsigned qf[16][4];
    const int qrow = warp * 16 + lq;
#pragma unroll
    for (int ks = 0; ks < 16; ks++) {
        qf[ks][0] = __float_as_uint(sK[qrow * KSTRIDE + ks * 8 + lr]);
        qf[ks][1] = __float_as_uint(sK[(qrow + 8) * KSTRIDE + ks * 8 + lr]);
        qf[ks][2] = __float_as_uint(sK[qrow * KSTRIDE + ks * 8 + lr + 4]);
        qf[ks][3] = __float_as_uint(sK[(qrow + 8) * KSTRIDE + ks * 8 + lr + 4]);
    }
    __syncthreads();

    float o[16][4];
#pragma unroll
    for (int jn = 0; jn < 16; jn++)
#pragma unroll
        for (int t = 0; t < 4; t++) o[jn][t] = 0.f;
    float m0 = -INFINITY, m1 = -INFINITY, l0 = 0.f, l1 = 0.f;

    for (int kt = 0; kt < SEQ / 64; kt++) {
        const size_t kb = baseK + (size_t)kt * 64 * DIM;
        for (int idx = tid; idx < 64 * 32; idx += 128) {
            int r = idx >> 5, c4 = (idx & 31) << 2;
            *(float4*)(sK + r * KSTRIDE + c4) =
                *(const float4*)(K + kb + (size_t)r * DIM + c4);
            *(float4*)(sV + r * KSTRIDE + c4) =
                *(const float4*)(V + kb + (size_t)r * DIM + c4);
        }
        __syncthreads();

        float sacc[8][4];
#pragma unroll
        for (int j = 0; j < 8; j++)
#pragma unroll
            for (int t = 0; t < 4; t++) sacc[j][t] = 0.f;

#pragma unroll
        for (int ks = 0; ks < 16; ks++) {
#pragma unroll
            for (int j = 0; j < 8; j++) {
                unsigned bf[2];
                bf[0] = __float_as_uint(sK[(j * 8 + lq) * KSTRIDE + ks * 8 + lr]);
                bf[1] = __float_as_uint(sK[(j * 8 + lq) * KSTRIDE + ks * 8 + lr + 4]);
                mma_tf32(sacc[j], qf[ks], bf);
            }
        }

        float mx0 = -INFINITY, mx1 = -INFINITY;
#pragma unroll
        for (int j = 0; j < 8; j++) {
            sacc[j][0] *= scale; sacc[j][1] *= scale;
            sacc[j][2] *= scale; sacc[j][3] *= scale;
            mx0 = fmaxf(mx0, fmaxf(sacc[j][0], sacc[j][1]));
            mx1 = fmaxf(mx1, fmaxf(sacc[j][2], sacc[j][3]));
        }
        mx0 = fmaxf(mx0, __shfl_xor_sync(0xffffffffu, mx0, 1));
        mx0 = fmaxf(mx0, __shfl_xor_sync(0xffffffffu, mx0, 2));
        mx1 = fmaxf(mx1, __shfl_xor_sync(0xffffffffu, mx1, 1));
        mx1 = fmaxf(mx1, __shfl_xor_sync(0xffffffffu, mx1, 2));

        float mn0 = fmaxf(m0, mx0), mn1 = fmaxf(m1, mx1);
        float al0 = __expf(m0 - mn0), al1 = __expf(m1 - mn1);
        m0 = mn0; m1 = mn1;

        unsigned pb[8][4];
        float sum0 = 0.f, sum1 = 0.f;
#pragma unroll
        for (int j = 0; j < 8; j++) {
            float p0 = __expf(sacc[j][0] - mn0);
            float p1 = __expf(sacc[j][1] - mn0);
            float p2 = __expf(sacc[j][2] - mn1);
            float p3 = __expf(sacc[j][3] - mn1);
            sum0 += p0 + p1; sum1 += p2 + p3;
            pb[j][0] = f2tf32(p0); pb[j][1] = f2tf32(p1);
            pb[j][2] = f2tf32(p2); pb[j][3] = f2tf32(p3);
        }
        sum0 += __shfl_xor_sync(0xffffffffu, sum0, 1);
        sum0 += __shfl_xor_sync(0xffffffffu, sum0, 2);
        sum1 += __shfl_xor_sync(0xffffffffu, sum1, 1);
        sum1 += __shfl_xor_sync(0xffffffffu, sum1, 2);
        l0 = l0 * al0 + sum0;
        l1 = l1 * al1 + sum1;

#pragma unroll
        for (int jn = 0; jn < 16; jn++) {
            o[jn][0] *= al0; o[jn][1] *= al0;
            o[jn][2] *= al1; o[jn][3] *= al1;
        }

        const int srcl = lq * 4 + (lr >> 1);
#pragma unroll
        for (int k8 = 0; k8 < 8; k8++) {
            unsigned a[4];
            unsigned t00 = __shfl_sync(0xffffffffu, pb[k8][0], srcl);
            unsigned t01 = __shfl_sync(0xffffffffu, pb[k8][1], srcl);
            unsigned t10 = __shfl_sync(0xffffffffu, pb[k8][2], srcl);
            unsigned t11 = __shfl_sync(0xffffffffu, pb[k8][3], srcl);
            unsigned u00 = __shfl_sync(0xffffffffu, pb[k8][0], srcl + 2);
            unsigned u01 = __shfl_sync(0xffffffffu, pb[k8][1], srcl + 2);
            unsigned u10 = __shfl_sync(0xffffffffu, pb[k8][2], srcl + 2);
            unsigned u11 = __shfl_sync(0xffffffffu, pb[k8][3], srcl + 2);
            a[0] = (lr & 1) ? t01 : t00;
            a[1] = (lr & 1) ? t11 : t10;
            a[2] = (lr & 1) ? u01 : u00;
            a[3] = (lr & 1) ? u11 : u10;
#pragma unroll
            for (int jn = 0; jn < 16; jn++) {
                unsigned bf[2];
                bf[0] = __float_as_uint(sV[(k8 * 8 + lr) * KSTRIDE + jn * 8 + lq]);
                bf[1] = __float_as_uint(sV[(k8 * 8 + lr + 4) * KSTRIDE + jn * 8 + lq]);
                mma_tf32(o[jn], a, bf);
            }
        }
        __syncthreads();
    }

    const float inv0 = 1.0f / l0, inv1 = 1.0f / l1;
    float* Orow0 = O + baseQ + (size_t)qrow * DIM;
    float* Orow1 = O + baseQ + (size_t)(qrow + 8) * DIM;
#pragma unroll
    for (int jn = 0; jn < 16; jn++) {
        int c = jn * 8 + 2 * lr;
        *(float2*)(Orow0 + c) = make_float2(o[jn][0] * inv0, o[jn][1] * inv0);
        *(float2*)(Orow1 + c) = make_float2(o[jn][2] * inv1, o[jn][3] * inv1);
    }
}

// ---------------------------------------------------------------------------
extern "C" void kernel_launch(void* const* d_in, const int* in_sizes, int n_in,
                              void* d_out, int out_size)
{
    const float* x      = (const float*)d_in[0];
    const float* Wq     = (const float*)d_in[1];
    const float* bq     = (const float*)d_in[2];
    const float* Wk     = (const float*)d_in[3];
    const float* bk     = (const float*)d_in[4];
    const float* Wv     = (const float*)d_in[5];
    const float* bv     = (const float*)d_in[6];
    const float* Wo     = (const float*)d_in[7];
    const float* bo     = (const float*)d_in[8];
    const float* spiral = (const float*)d_in[9];
    const float* rot    = (const float*)d_in[10];
    float* out = (float*)d_out;

    float *Qp, *Kp, *Vp, *Ap;
    cudaGetSymbolAddress((void**)&Qp, g_Q);
    cudaGetSymbolAddress((void**)&Kp, g_K);
    cudaGetSymbolAddress((void**)&Vp, g_V);
    cudaGetSymbolAddress((void**)&Ap, g_A);

    const int M = BATCH * SEQ;   // 8192

    cudaFuncSetAttribute(gemm_tf32_kernel,
                         cudaFuncAttributeMaxDynamicSharedMemorySize, GEMM_SMEM_BYTES);
    cudaFuncSetAttribute(flash_tf32_kernel,
                         cudaFuncAttributeMaxDynamicSharedMemorySize, FLASH_SMEM_BYTES);

    // fused QKV projection in ONE launch: z = blockIdx.x/16 selects W/bias/C
    gemm_tf32_kernel<<<dim3(48, M / 128), 256, GEMM_SMEM_BYTES>>>(
        x, rot,
        Wq, bq, Qp, 1,
        Wk, bk, Kp, 2,
        Wv, bv, Vp, 0,
        1);

    flash_tf32_kernel<<<dim3(SEQ / 64, NH, BATCH), 128, FLASH_SMEM_BYTES>>>(
        Qp, Kp, Vp, spiral, Ap);

    // output projection (single weight; z always 0)
    gemm_tf32_kernel<<<dim3(16, M / 128), 256, GEMM_SMEM_BYTES>>>(
        Ap, rot,
        Wo, bo, out, 0,
        Wo, bo, out, 0,
        Wo, bo, out, 0,
        0);
}

// round 17
// speedup vs baseline: 1.1164x; 1.0095x over previous
#include <cuda_runtime.h>
#include <math.h>
#include <stdint.h>

#define BATCH 4
#define SEQ   2048
#define DIM   2048
#define NH    16
#define DHEAD 128

__device__ float g_Q[BATCH * SEQ * DIM];
__device__ float g_K[BATCH * SEQ * DIM];
__device__ float g_V[BATCH * SEQ * DIM];
__device__ float g_A[BATCH * SEQ * DIM];

__device__ __forceinline__ unsigned f2tf32(float x) {
    unsigned u;
    asm("cvt.rna.tf32.f32 %0, %1;" : "=r"(u) : "f"(x));
    return u;
}
__device__ __forceinline__ void mma_tf32(float* d, const unsigned* a, const unsigned* b) {
    asm volatile(
        "mma.sync.aligned.m16n8k8.row.col.f32.tf32.tf32.f32 "
        "{%0,%1,%2,%3}, {%4,%5,%6,%7}, {%8,%9}, {%0,%1,%2,%3};\n"
        : "+f"(d[0]), "+f"(d[1]), "+f"(d[2]), "+f"(d[3])
        : "r"(a[0]), "r"(a[1]), "r"(a[2]), "r"(a[3]), "r"(b[0]), "r"(b[1]));
}

// ---------------------------------------------------------------------------
// TF32 NT GEMM (R6 inner loop), UNFUSED launches, __launch_bounds__(256,2)
// to guarantee <=128 regs -> 2 CTAs/SM.
// C = (A @ W^T + bias) * gate(mode); mode 0 none, 1 cos, 2 sin.
// ---------------------------------------------------------------------------
#define GSTRIDE 36
#define GBUF (128 * GSTRIDE)
#define GEMM_SMEM_BYTES (4 * GBUF * 4)   // 73728 -> fits 2 CTAs/SM

__global__ __launch_bounds__(256, 2) void gemm_tf32_kernel(
    const float* __restrict__ A, const float* __restrict__ rot,
    const float* __restrict__ W, const float* __restrict__ bias,
    float* __restrict__ C, int mode, int roundout)
{
    extern __shared__ unsigned sm[];
    unsigned* As = sm;
    unsigned* Bs = sm + 2 * GBUF;

    const int K = DIM, N = DIM;
    const int tid = threadIdx.x;
    const int warp = tid >> 5, lane = tid & 31;
    const int wm = (warp >> 2) * 64;
    const int wn = (warp & 3) * 32;
    const int bm = blockIdx.y * 128, bn = blockIdx.x * 128;

    const int lrow = tid >> 3;          // 0..31
    const int lcol = (tid & 7) * 4;     // 0..28

    float acc[4][4][4];
#pragma unroll
    for (int i = 0; i < 4; i++)
#pragma unroll
        for (int j = 0; j < 4; j++)
#pragma unroll
            for (int t = 0; t < 4; t++) acc[i][j][t] = 0.f;

    const float* Ag = A + (size_t)(bm + lrow) * K + lcol;
    const float* Wg = W + (size_t)(bn + lrow) * K + lcol;

    float4 ra[4], rb[4];

    auto G2R = [&](int kt) {
        const size_t ko = (size_t)kt * 32;
#pragma unroll
        for (int it = 0; it < 4; it++) {
            ra[it] = *(const float4*)(Ag + (size_t)it * 32 * K + ko);
            rb[it] = *(const float4*)(Wg + (size_t)it * 32 * K + ko);
        }
    };
    auto R2S = [&](int buf) {
#pragma unroll
        for (int it = 0; it < 4; it++) {
            int base = buf * GBUF + (lrow + it * 32) * GSTRIDE + lcol;
            uint4 ua = make_uint4(f2tf32(ra[it].x), f2tf32(ra[it].y),
                                  f2tf32(ra[it].z), f2tf32(ra[it].w));
            uint4 ub = make_uint4(f2tf32(rb[it].x), f2tf32(rb[it].y),
                                  f2tf32(rb[it].z), f2tf32(rb[it].w));
            *(uint4*)(As + base) = ua;
            *(uint4*)(Bs + base) = ub;
        }
    };

    const int ntiles = K / 32;   // 64
    G2R(0);
    R2S(0);
    __syncthreads();

    const int lq = lane >> 2;
    const int lr = lane & 3;

    for (int kt = 0; kt < ntiles; kt++) {
        if (kt + 1 < ntiles) G2R(kt + 1);

        const unsigned* Ab = As + (kt & 1) * GBUF;
        const unsigned* Bb = Bs + (kt & 1) * GBUF;
#pragma unroll
        for (int k8 = 0; k8 < 4; k8++) {
            const int kc = k8 * 8 + lr;
            unsigned af[4][4], bf[4][2];
#pragma unroll
            for (int i = 0; i < 4; i++) {
                int r = wm + i * 16 + lq;
                af[i][0] = Ab[r * GSTRIDE + kc];
                af[i][1] = Ab[(r + 8) * GSTRIDE + kc];
                af[i][2] = Ab[r * GSTRIDE + kc + 4];
                af[i][3] = Ab[(r + 8) * GSTRIDE + kc + 4];
            }
#pragma unroll
            for (int j = 0; j < 4; j++) {
                int c = wn + j * 8 + lq;
                bf[j][0] = Bb[c * GSTRIDE + kc];
                bf[j][1] = Bb[c * GSTRIDE + kc + 4];
            }
#pragma unroll
            for (int i = 0; i < 4; i++)
#pragma unroll
                for (int j = 0; j < 4; j++)
                    mma_tf32(acc[i][j], af[i], bf[j]);
        }

        if (kt + 1 < ntiles) R2S((kt + 1) & 1);
        __syncthreads();
    }

    // epilogue: bias + optional cos/sin gate, optional tf32 rounding
#pragma unroll
    for (int j = 0; j < 4; j++) {
        int c0 = bn + wn + j * 8 + (lr << 1);
        float bb0 = __ldg(bias + c0), bb1 = __ldg(bias + c0 + 1);
        float g0 = 1.f, g1 = 1.f;
        if (mode == 1) { g0 = cosf(__ldg(rot + c0)); g1 = cosf(__ldg(rot + c0 + 1)); }
        else if (mode == 2) { g0 = sinf(__ldg(rot + c0)); g1 = sinf(__ldg(rot + c0 + 1)); }
#pragma unroll
        for (int i = 0; i < 4; i++) {
            int r0 = bm + wm + i * 16 + lq;
            float v00 = (acc[i][j][0] + bb0) * g0, v01 = (acc[i][j][1] + bb1) * g1;
            float v10 = (acc[i][j][2] + bb0) * g0, v11 = (acc[i][j][3] + bb1) * g1;
            if (roundout) {
                v00 = __uint_as_float(f2tf32(v00)); v01 = __uint_as_float(f2tf32(v01));
                v10 = __uint_as_float(f2tf32(v10)); v11 = __uint_as_float(f2tf32(v11));
            }
            *(float2*)(C + (size_t)r0 * N + c0)       = make_float2(v00, v01);
            *(float2*)(C + (size_t)(r0 + 8) * N + c0) = make_float2(v10, v11);
        }
    }
}

// ---------------------------------------------------------------------------
// TF32 mma.sync flash attention (R6 known-good, unchanged).
// BM=64 (4 warps x 16 rows), BN=64, DH=128, 128 threads, 2 CTAs/SM.
// ---------------------------------------------------------------------------
#define KSTRIDE 132
#define FLASH_SMEM_BYTES (2 * 64 * KSTRIDE * 4)

__global__ __launch_bounds__(128) void flash_tf32_kernel(
    const float* __restrict__ Q, const float* __restrict__ K,
    const float* __restrict__ V, const float* __restrict__ spiral,
    float* __restrict__ O)
{
    extern __shared__ float fs[];
    float* sK = fs;
    float* sV = fs + 64 * KSTRIDE;

    const int tid = threadIdx.x;
    const int warp = tid >> 5, lane = tid & 31;
    const int lq = lane >> 2, lr = lane & 3;
    const int qt = blockIdx.x, h = blockIdx.y, b = blockIdx.z;
    const int s0 = qt * 64;
    const float scale = spiral[h] * 0.08838834764831845f;

    const size_t baseQ = ((size_t)b * SEQ + s0) * DIM + (size_t)h * DHEAD;
    const size_t baseK = (size_t)b * SEQ * DIM + (size_t)h * DHEAD;

    for (int idx = tid; idx < 64 * 32; idx += 128) {
        int r = idx >> 5, c4 = (idx & 31) << 2;
        *(float4*)(sK + r * KSTRIDE + c4) =
            *(const float4*)(Q + baseQ + (size_t)r * DIM + c4);
    }
    __syncthreads();

    unsigned qf[16][4];
    const int qrow = warp * 16 + lq;
#pragma unroll
    for (int ks = 0; ks < 16; ks++) {
        qf[ks][0] = __float_as_uint(sK[qrow * KSTRIDE + ks * 8 + lr]);
        qf[ks][1] = __float_as_uint(sK[(qrow + 8) * KSTRIDE + ks * 8 + lr]);
        qf[ks][2] = __float_as_uint(sK[qrow * KSTRIDE + ks * 8 + lr + 4]);
        qf[ks][3] = __float_as_uint(sK[(qrow + 8) * KSTRIDE + ks * 8 + lr + 4]);
    }
    __syncthreads();

    float o[16][4];
#pragma unroll
    for (int jn = 0; jn < 16; jn++)
#pragma unroll
        for (int t = 0; t < 4; t++) o[jn][t] = 0.f;
    float m0 = -INFINITY, m1 = -INFINITY, l0 = 0.f, l1 = 0.f;

    for (int kt = 0; kt < SEQ / 64; kt++) {
        const size_t kb = baseK + (size_t)kt * 64 * DIM;
        for (int idx = tid; idx < 64 * 32; idx += 128) {
            int r = idx >> 5, c4 = (idx & 31) << 2;
            *(float4*)(sK + r * KSTRIDE + c4) =
                *(const float4*)(K + kb + (size_t)r * DIM + c4);
            *(float4*)(sV + r * KSTRIDE + c4) =
                *(const float4*)(V + kb + (size_t)r * DIM + c4);
        }
        __syncthreads();

        float sacc[8][4];
#pragma unroll
        for (int j = 0; j < 8; j++)
#pragma unroll
            for (int t = 0; t < 4; t++) sacc[j][t] = 0.f;

#pragma unroll
        for (int ks = 0; ks < 16; ks++) {
#pragma unroll
            for (int j = 0; j < 8; j++) {
                unsigned bf[2];
                bf[0] = __float_as_uint(sK[(j * 8 + lq) * KSTRIDE + ks * 8 + lr]);
                bf[1] = __float_as_uint(sK[(j * 8 + lq) * KSTRIDE + ks * 8 + lr + 4]);
                mma_tf32(sacc[j], qf[ks], bf);
            }
        }

        float mx0 = -INFINITY, mx1 = -INFINITY;
#pragma unroll
        for (int j = 0; j < 8; j++) {
            sacc[j][0] *= scale; sacc[j][1] *= scale;
            sacc[j][2] *= scale; sacc[j][3] *= scale;
            mx0 = fmaxf(mx0, fmaxf(sacc[j][0], sacc[j][1]));
            mx1 = fmaxf(mx1, fmaxf(sacc[j][2], sacc[j][3]));
        }
        mx0 = fmaxf(mx0, __shfl_xor_sync(0xffffffffu, mx0, 1));
        mx0 = fmaxf(mx0, __shfl_xor_sync(0xffffffffu, mx0, 2));
        mx1 = fmaxf(mx1, __shfl_xor_sync(0xffffffffu, mx1, 1));
        mx1 = fmaxf(mx1, __shfl_xor_sync(0xffffffffu, mx1, 2));

        float mn0 = fmaxf(m0, mx0), mn1 = fmaxf(m1, mx1);
        float al0 = __expf(m0 - mn0), al1 = __expf(m1 - mn1);
        m0 = mn0; m1 = mn1;

        unsigned pb[8][4];
        float sum0 = 0.f, sum1 = 0.f;
#pragma unroll
        for (int j = 0; j < 8; j++) {
            float p0 = __expf(sacc[j][0] - mn0);
            float p1 = __expf(sacc[j][1] - mn0);
            float p2 = __expf(sacc[j][2] - mn1);
            float p3 = __expf(sacc[j][3] - mn1);
            sum0 += p0 + p1; sum1 += p2 + p3;
            pb[j][0] = f2tf32(p0); pb[j][1] = f2tf32(p1);
            pb[j][2] = f2tf32(p2); pb[j][3] = f2tf32(p3);
        }
        sum0 += __shfl_xor_sync(0xffffffffu, sum0, 1);
        sum0 += __shfl_xor_sync(0xffffffffu, sum0, 2);
        sum1 += __shfl_xor_sync(0xffffffffu, sum1, 1);
        sum1 += __shfl_xor_sync(0xffffffffu, sum1, 2);
        l0 = l0 * al0 + sum0;
        l1 = l1 * al1 + sum1;

#pragma unroll
        for (int jn = 0; jn < 16; jn++) {
            o[jn][0] *= al0; o[jn][1] *= al0;
            o[jn][2] *= al1; o[jn][3] *= al1;
        }

        const int srcl = lq * 4 + (lr >> 1);
#pragma unroll
        for (int k8 = 0; k8 < 8; k8++) {
            unsigned a[4];
            unsigned t00 = __shfl_sync(0xffffffffu, pb[k8][0], srcl);
            unsigned t01 = __shfl_sync(0xffffffffu, pb[k8][1], srcl);
            unsigned t10 = __shfl_sync(0xffffffffu, pb[k8][2], srcl);
            unsigned t11 = __shfl_sync(0xffffffffu, pb[k8][3], srcl);
            unsigned u00 = __shfl_sync(0xffffffffu, pb[k8][0], srcl + 2);
            unsigned u01 = __shfl_sync(0xffffffffu, pb[k8][1], srcl + 2);
            unsigned u10 = __shfl_sync(0xffffffffu, pb[k8][2], srcl + 2);
            unsigned u11 = __shfl_sync(0xffffffffu, pb[k8][3], srcl + 2);
            a[0] = (lr & 1) ? t01 : t00;
            a[1] = (lr & 1) ? t11 : t10;
            a[2] = (lr & 1) ? u01 : u00;
            a[3] = (lr & 1) ? u11 : u10;
#pragma unroll
            for (int jn = 0; jn < 16; jn++) {
                unsigned bf[2];
                bf[0] = __float_as_uint(sV[(k8 * 8 + lr) * KSTRIDE + jn * 8 + lq]);
                bf[1] = __float_as_uint(sV[(k8 * 8 + lr + 4) * KSTRIDE + jn * 8 + lq]);
                mma_tf32(o[jn], a, bf);
            }
        }
        __syncthreads();
    }

    const float inv0 = 1.0f / l0, inv1 = 1.0f / l1;
    float* Orow0 = O + baseQ + (size_t)qrow * DIM;
    float* Orow1 = O + baseQ + (size_t)(qrow + 8) * DIM;
#pragma unroll
    for (int jn = 0; jn < 16; jn++) {
        int c = jn * 8 + 2 * lr;
        *(float2*)(Orow0 + c) = make_float2(o[jn][0] * inv0, o[jn][1] * inv0);
        *(float2*)(Orow1 + c) = make_float2(o[jn][2] * inv1, o[jn][3] * inv1);
    }
}

// ---------------------------------------------------------------------------
extern "C" void kernel_launch(void* const* d_in, const int* in_sizes, int n_in,
                              void* d_out, int out_size)
{
    const float* x      = (const float*)d_in[0];
    const float* Wq     = (const float*)d_in[1];
    const float* bq     = (const float*)d_in[2];
    const float* Wk     = (const float*)d_in[3];
    const float* bk     = (const float*)d_in[4];
    const float* Wv     = (const float*)d_in[5];
    const float* bv     = (const float*)d_in[6];
    const float* Wo     = (const float*)d_in[7];
    const float* bo     = (const float*)d_in[8];
    const float* spiral = (const float*)d_in[9];
    const float* rot    = (const float*)d_in[10];
    float* out = (float*)d_out;

    float *Qp, *Kp, *Vp, *Ap;
    cudaGetSymbolAddress((void**)&Qp, g_Q);
    cudaGetSymbolAddress((void**)&Kp, g_K);
    cudaGetSymbolAddress((void**)&Vp, g_V);
    cudaGetSymbolAddress((void**)&Ap, g_A);

    const int M = BATCH * SEQ;   // 8192
    dim3 gg(DIM / 128, M / 128); // 16 x 64

    cudaFuncSetAttribute(gemm_tf32_kernel,
                         cudaFuncAttributeMaxDynamicSharedMemorySize, GEMM_SMEM_BYTES);
    cudaFuncSetAttribute(flash_tf32_kernel,
                         cudaFuncAttributeMaxDynamicSharedMemorySize, FLASH_SMEM_BYTES);

    gemm_tf32_kernel<<<gg, 256, GEMM_SMEM_BYTES>>>(x, rot, Wq, bq, Qp, 1, 1);
    gemm_tf32_kernel<<<gg, 256, GEMM_SMEM_BYTES>>>(x, rot, Wk, bk, Kp, 2, 1);
    gemm_tf32_kernel<<<gg, 256, GEMM_SMEM_BYTES>>>(x, rot, Wv, bv, Vp, 0, 1);

    flash_tf32_kernel<<<dim3(SEQ / 64, NH, BATCH), 128, FLASH_SMEM_BYTES>>>(
        Qp, Kp, Vp, spiral, Ap);

    gemm_tf32_kernel<<<gg, 256, GEMM_SMEM_BYTES>>>(Ap, rot, Wo, bo, out, 0, 0);
}